// round 16
// baseline (speedup 1.0000x reference)
#include <cuda_runtime.h>
#include <cuda_fp16.h>
#include <cstdint>

#define B_SZ   8
#define T_SEQ  1024
#define C_DIM  768
#define C3     2304
#define NH     12
#define HS     64
#define SCALE_F 0.125f
#define M_ROWS (B_SZ * T_SEQ)       /* 8192 */
#define NBH    (B_SZ * NH)          /* 96 */

// fp16 operands: x [8192,768], W^T [2304,768] (K-contiguous)
__device__ __align__(16) __half g_xh[(size_t)M_ROWS * C_DIM];
__device__ __align__(16) __half g_wth[(size_t)C3 * C_DIM];
// head-separated QKV outputs, fp16: [bh, t, 64]. g_q is pre-scaled by 1/8.
#define QKV_ELEMS ((size_t)NBH * T_SEQ * HS)
__device__ __align__(16) __half g_q[QKV_ELEMS], g_k[QKV_ELEMS], g_v[QKV_ELEMS];

// ---------------------------------------------------------------------------
// helpers
// ---------------------------------------------------------------------------
__device__ __forceinline__ uint32_t smem_u32(const void* p) {
    uint32_t a;
    asm("{ .reg .u64 t; cvta.to.shared.u64 t, %1; cvt.u32.u64 %0, t; }"
        : "=r"(a) : "l"(p));
    return a;
}
#define SWZ128(off) ((off) ^ (((off) >> 3) & 0x70))

__device__ __forceinline__ void cp_async16(uint32_t saddr, const void* gaddr) {
    asm volatile("cp.async.cg.shared.global [%0], [%1], 16;"
                 :: "r"(saddr), "l"(gaddr) : "memory");
}
__device__ __forceinline__ void cp_commit() {
    asm volatile("cp.async.commit_group;" ::: "memory");
}
template <int N>
__device__ __forceinline__ void cp_wait() {
    asm volatile("cp.async.wait_group %0;" :: "n"(N) : "memory");
}
__device__ __forceinline__ void ldm_x4(uint32_t* r, uint32_t addr) {
    asm volatile("ldmatrix.sync.aligned.m8n8.x4.shared.b16 {%0,%1,%2,%3}, [%4];"
                 : "=r"(r[0]), "=r"(r[1]), "=r"(r[2]), "=r"(r[3]) : "r"(addr));
}
__device__ __forceinline__ void ldm_x4_t(uint32_t* r, uint32_t addr) {
    asm volatile("ldmatrix.sync.aligned.m8n8.x4.trans.shared.b16 {%0,%1,%2,%3}, [%4];"
                 : "=r"(r[0]), "=r"(r[1]), "=r"(r[2]), "=r"(r[3]) : "r"(addr));
}
__device__ __forceinline__ void mma_f16(float* c, const uint32_t* a,
                                        const uint32_t b0, const uint32_t b1) {
    asm volatile(
        "mma.sync.aligned.m16n8k16.row.col.f32.f16.f16.f32 "
        "{%0,%1,%2,%3}, {%4,%5,%6,%7}, {%8,%9}, {%0,%1,%2,%3};"
        : "+f"(c[0]), "+f"(c[1]), "+f"(c[2]), "+f"(c[3])
        : "r"(a[0]), "r"(a[1]), "r"(a[2]), "r"(a[3]), "r"(b0), "r"(b1));
}
__device__ __forceinline__ uint32_t pack_f16x2(float v0, float v1) {
    __half2 h = __floats2half2_rn(v0, v1);   // v0 -> low
    return *reinterpret_cast<uint32_t*>(&h);
}
// pack + relu in fp16x2 (identical numerics to cvt(max(v,0)))
__device__ __forceinline__ uint32_t pack_relu_f16x2(float v0, float v1) {
    __half2 h = __floats2half2_rn(v0, v1);
    h = __hmax2(h, __half2half2(__ushort_as_half(0)));
    return *reinterpret_cast<uint32_t*>(&h);
}

// ---------------------------------------------------------------------------
// Prep kernels: fp16 convert of x (x8 vectorized); transpose+convert of W
// ---------------------------------------------------------------------------
__global__ void prep_x_kernel(const float* __restrict__ x) {
    int i = (blockIdx.x * blockDim.x + threadIdx.x) * 8;   // grid sized exactly
    float4 a = *(const float4*)(x + i);
    float4 b = *(const float4*)(x + i + 4);
    uint4 o;
    o.x = pack_f16x2(a.x, a.y);
    o.y = pack_f16x2(a.z, a.w);
    o.z = pack_f16x2(b.x, b.y);
    o.w = pack_f16x2(b.z, b.w);
    *(uint4*)(g_xh + i) = o;
}

__global__ void prep_w_kernel(const float* __restrict__ W) {
    __shared__ float t[32][33];
    int n0 = blockIdx.x * 32, k0 = blockIdx.y * 32;
    int tx = threadIdx.x, ty = threadIdx.y;
#pragma unroll
    for (int j = 0; j < 4; j++)
        t[ty + 8 * j][tx] = W[(size_t)(k0 + ty + 8 * j) * C3 + n0 + tx];
    __syncthreads();
#pragma unroll
    for (int jj = 0; jj < 2; jj++) {
        int idx = jj * 256 + ty * 32 + tx;   // 0..511
        int r   = idx >> 4;                  // n-row 0..31
        int kp  = idx & 15;                  // k-pair 0..15
        uint32_t v = pack_f16x2(t[2 * kp][r], t[2 * kp + 1][r]);
        *(uint32_t*)(g_wth + (size_t)(n0 + r) * C_DIM + k0 + 2 * kp) = v;
    }
}

// ---------------------------------------------------------------------------
// Kernel 1: QKV projection, fp16 mma.sync (R14 exact, measured best).
// Block tile 128x128, K-chunk 64, 8 warps (warp 32x64), 2-stage, 2 CTA/SM.
// Epilogue: smem-staged, fully coalesced 128B-row stores.
// ---------------------------------------------------------------------------
#define BK       64
#define NCHUNK   (C_DIM / BK)          /* 12 */
#define TILE_B   (128 * 128)           /* 16 KB */
#define STAGE_B  (2 * TILE_B)          /* A + B = 32 KB */
#define GEMM_SMEM (2 * STAGE_B)        /* 64 KB */
#define EPI_STRIDE 72                  /* halves per staged row (pad: 64+8) */
#define EPI_WARP_B (32 * EPI_STRIDE * 2)   /* 4608 B per warp */

__device__ __forceinline__ void load_stage(uint32_t sbase, int bm, int bn,
                                           int k0, int tid)
{
#pragma unroll
    for (int i = 0; i < 8; i++) {
        int lin = i * 256 + tid;          // 0..2047
        int buf = lin >> 10;              // 0:A 1:B
        int idx = lin & 1023;
        int r   = idx >> 3;
        int cb  = (idx & 7) * 16;
        uint32_t sw = SWZ128((uint32_t)(r * 128 + cb));
        const char* src = buf
            ? (const char*)(g_wth + (size_t)(bn + r) * C_DIM + k0) + cb
            : (const char*)(g_xh  + (size_t)(bm + r) * C_DIM + k0) + cb;
        cp_async16(sbase + buf * TILE_B + sw, src);
    }
    cp_commit();
}

__global__ __launch_bounds__(256, 2) void qkv_mma_kernel(const float* __restrict__ bias)
{
    extern __shared__ char sm[];
    const uint32_t sbase = smem_u32(sm);

    const int tid  = threadIdx.x;
    const int wid  = tid >> 5;
    const int lane = tid & 31;
    const int bn   = blockIdx.x * 128;
    const int bm   = blockIdx.y * 128;
    const int warp_m = (wid & 3) * 32;
    const int warp_n = (wid >> 2) * 64;
    const int ldrow   = lane & 15;
    const int ldchunk = (lane >> 4) * 16;

    float acc[2][8][4];
#pragma unroll
    for (int mt = 0; mt < 2; mt++)
#pragma unroll
        for (int nt = 0; nt < 8; nt++)
#pragma unroll
            for (int q = 0; q < 4; q++) acc[mt][nt][q] = 0.f;

    load_stage(sbase, bm, bn, 0, tid);

    for (int ch = 0; ch < NCHUNK; ch++) {
        const uint32_t sstage = sbase + (uint32_t)(ch & 1) * STAGE_B;
        if (ch + 1 < NCHUNK) {
            load_stage(sbase + (uint32_t)((ch + 1) & 1) * STAGE_B,
                       bm, bn, (ch + 1) * BK, tid);
            cp_wait<1>();
        } else {
            cp_wait<0>();
        }
        __syncthreads();

#pragma unroll
        for (int ks = 0; ks < 4; ks++) {
            const int kb = ks * 32 + ldchunk;
            uint32_t a[2][4];
#pragma unroll
            for (int mt = 0; mt < 2; mt++) {
                uint32_t off = SWZ128((uint32_t)((warp_m + mt * 16 + ldrow) * 128 + kb));
                ldm_x4(a[mt], sstage + off);
            }
            uint32_t bv[8][2];
#pragma unroll
            for (int np = 0; np < 4; np++) {
                uint32_t off = SWZ128((uint32_t)((warp_n + np * 16 + ldrow) * 128 + kb));
                uint32_t r[4];
                ldm_x4(r, sstage + TILE_B + off);
                bv[2 * np][0] = r[0]; bv[2 * np][1] = r[2];
                bv[2 * np + 1][0] = r[1]; bv[2 * np + 1][1] = r[3];
            }
#pragma unroll
            for (int mt = 0; mt < 2; mt++)
#pragma unroll
                for (int nt = 0; nt < 8; nt++)
                    mma_f16(acc[mt][nt], a[mt], bv[nt][0], bv[nt][1]);
        }
        __syncthreads();
    }

    // ---- Epilogue: bias + stage to smem, then coalesced 128B-row stores ----
    const int col0  = bn + warp_n;            // 64-aligned
    const int which = col0 / C_DIM;
    const int hh    = (col0 % C_DIM) / HS;
    __half* dst = (which == 0) ? g_q : (which == 1) ? g_k : g_v;
    const float scl = (which == 0) ? SCALE_F : 1.f;

    char* wst = sm + wid * EPI_WARP_B;
    const int crow = lane >> 2;
    const int ccol = (lane & 3) * 2;
#pragma unroll
    for (int mt = 0; mt < 2; mt++) {
#pragma unroll
        for (int nt = 0; nt < 8; nt++) {
            int ncol = nt * 8 + ccol;
            float2 bb = *(const float2*)(bias + col0 + ncol);
#pragma unroll
            for (int p = 0; p < 2; p++) {
                int lrow = mt * 16 + p * 8 + crow;
                uint32_t hv = pack_f16x2((acc[mt][nt][2 * p + 0] + bb.x) * scl,
                                         (acc[mt][nt][2 * p + 1] + bb.y) * scl);
                *(uint32_t*)(wst + (lrow * EPI_STRIDE + ncol) * 2) = hv;
            }
        }
    }
    __syncwarp();

    const int rbase = bm + warp_m;
#pragma unroll
    for (int it = 0; it < 8; it++) {
        int idx = it * 32 + lane;
        int lrow = idx >> 3;
        int chk  = idx & 7;
        int r = rbase + lrow;
        int bidx = r >> 10, t = r & 1023;
        size_t off = (((size_t)(bidx * NH + hh)) * T_SEQ + t) * HS + chk * 8;
        uint4 v = *(uint4*)(wst + (lrow * EPI_STRIDE + chk * 8) * 2);
        *(uint4*)(dst + off) = v;
    }
}

// ---------------------------------------------------------------------------
// Kernel 2: causal relu-attention, fp16 mma.sync.
// Block = (bh, 128 q-rows); 8 warps x 16 q-rows; kv-tile 64.
// SOFTWARE-PIPELINED S/Y: iteration it computes S_it AND issues Y_{it-1}
// in one region (independent mma bursts interleave). 4-stage kv ring.
// Q fragments resident in registers. 2 CTAs/SM.
// ---------------------------------------------------------------------------
#define AQ      0
#define ASTG    16384
#define ASTG_SZ 16384                  /* K 8KB + V 8KB */
#define AK      0
#define AV      8192
#define ANSTG   4
#define ATTN_SMEM (ASTG + ANSTG * ASTG_SZ)   /* 80 KB */

__device__ __forceinline__ void load_kv_stage(uint32_t dst, int bh, int kv0, int tid) {
#pragma unroll
    for (int i = 0; i < 4; i++) {
        int lin = i * 256 + tid;          // 0..1023
        int buf = lin >> 9;               // 0:K 1:V
        int idx = lin & 511;
        int r = idx >> 3, cb = (idx & 7) * 16;
        uint32_t sw = SWZ128((uint32_t)(r * 128 + cb));
        const __half* src = buf ? g_v : g_k;
        cp_async16(dst + buf * 8192 + sw,
                   (const char*)(src + ((size_t)bh * T_SEQ + kv0 + r) * HS) + cb);
    }
    cp_commit();
}

// Compute S for kv tile `it`, relu/mask, write fp16 A-frags into af[4][4].
__device__ __forceinline__ void compute_S(uint32_t sbQ, uint32_t stg,
                                          const uint32_t qf[4][4],
                                          uint32_t af[4][4],
                                          int qt, int it, int wm, int lane)
{
    const bool nomask = (it < 2 * qt);
#pragma unroll
    for (int hf = 0; hf < 2; hf++) {
        float s[4][4];
#pragma unroll
        for (int j = 0; j < 4; j++)
#pragma unroll
            for (int q = 0; q < 4; q++) s[j][q] = 0.f;

#pragma unroll
        for (int ks = 0; ks < 4; ks++) {
            const int kb = ks * 32 + (lane >> 4) * 16;
            uint32_t kf[4][2];
#pragma unroll
            for (int npl = 0; npl < 2; npl++) {
                int np = 2 * hf + npl;
                uint32_t koff = SWZ128((uint32_t)((np * 16 + (lane & 15)) * 128 + kb));
                uint32_t r[4];
                ldm_x4(r, stg + AK + koff);
                kf[2 * npl][0] = r[0]; kf[2 * npl][1] = r[2];
                kf[2 * npl + 1][0] = r[1]; kf[2 * npl + 1][1] = r[3];
            }
#pragma unroll
            for (int j = 0; j < 4; j++)
                mma_f16(s[j], qf[ks], kf[j][0], kf[j][1]);
        }

        if (nomask) {
#pragma unroll
            for (int j = 0; j < 4; j++) {
                int nt = 4 * hf + j;
#pragma unroll
                for (int p = 0; p < 2; p++)
                    af[nt >> 1][(nt & 1) * 2 + p] =
                        pack_relu_f16x2(s[j][2 * p + 0], s[j][2 * p + 1]);
            }
        } else {
            int q0 = qt * 128 + wm + (lane >> 2);
#pragma unroll
            for (int j = 0; j < 4; j++) {
                int nt  = 4 * hf + j;
                int kv0 = it * 64 + nt * 8 + (lane & 3) * 2;
#pragma unroll
                for (int p = 0; p < 2; p++) {
                    int qq = q0 + p * 8;
                    float v0 = (kv0     <= qq) ? fmaxf(s[j][2 * p + 0], 0.f) : 0.f;
                    float v1 = (kv0 + 1 <= qq) ? fmaxf(s[j][2 * p + 1], 0.f) : 0.f;
                    af[nt >> 1][(nt & 1) * 2 + p] = pack_f16x2(v0, v1);
                }
            }
        }
    }
}

// Y += S·V for one kv tile (V in stage `stg`, A-frags in af).
__device__ __forceinline__ void compute_Y(uint32_t stg, const uint32_t af[4][4],
                                          float accY[8][4], int lane)
{
#pragma unroll
    for (int ks = 0; ks < 4; ks++) {
#pragma unroll
        for (int np = 0; np < 4; np++) {
            uint32_t voff = SWZ128((uint32_t)(
                (ks * 16 + (lane & 7) + ((lane >> 4) & 1) * 8) * 128
                + np * 32 + ((lane >> 3) & 1) * 16));
            uint32_t vf[4];
            ldm_x4_t(vf, stg + AV + voff);
            mma_f16(accY[2 * np],     af[ks], vf[0], vf[2]);
            mma_f16(accY[2 * np + 1], af[ks], vf[1], vf[3]);
        }
    }
}

__global__ __launch_bounds__(256, 2) void attn_mma_kernel(float* __restrict__ out)
{
    extern __shared__ char sm[];
    const uint32_t sb = smem_u32(sm);
    const int tid = threadIdx.x, wid = tid >> 5, lane = tid & 31;
    const int qt = gridDim.x - 1 - blockIdx.x;   // heavy blocks first
    const int bh = blockIdx.y;
    const int b = bh / NH, h = bh % NH;
    const int wm = wid * 16;                     // warp owns 16 q-rows

    // Q tile load (group 1), then kv stages 0 and 1 (groups 2, 3)
#pragma unroll
    for (int i = 0; i < 4; i++) {
        int idx = i * 256 + tid;
        int r = idx >> 3, cb = (idx & 7) * 16;
        uint32_t sw = SWZ128((uint32_t)(r * 128 + cb));
        cp_async16(sb + AQ + sw,
                   (const char*)(g_q + ((size_t)bh * T_SEQ + qt * 128 + r) * HS) + cb);
    }
    cp_commit();
    load_kv_stage(sb + ASTG, bh, 0, tid);
    load_kv_stage(sb + ASTG + ASTG_SZ, bh, 64, tid);

    // Q ready (2 kv groups pending); publish; lift Q frags to registers.
    cp_wait<2>();
    __syncthreads();
    uint32_t qf[4][4];
#pragma unroll
    for (int ks = 0; ks < 4; ks++) {
        uint32_t qoff = SWZ128((uint32_t)((wm + (lane & 15)) * 128
                                          + ks * 32 + (lane >> 4) * 16));
        ldm_x4(qf[ks], sb + AQ + qoff);
    }

    float accY[8][4];
#pragma unroll
    for (int nt = 0; nt < 8; nt++)
#pragma unroll
        for (int q = 0; q < 4; q++) accY[nt][q] = 0.f;

    uint32_t af_prev[4][4], af_cur[4][4];

    const int niter = 2 * qt + 2;   // >= 2 always
    for (int it = 0; it < niter; it++) {
        if (it + 1 < niter) cp_wait<1>(); else cp_wait<0>();
        __syncthreads();   // stage it visible; all warps done with iter it-1

        const uint32_t stg_cur = sb + ASTG + (uint32_t)(it % ANSTG) * ASTG_SZ;

        // S_it and Y_{it-1} are independent -> one long interleavable burst
        compute_S(sb, stg_cur, qf, af_cur, qt, it, wm, lane);
        if (it > 0) {
            const uint32_t stg_prev = sb + ASTG
                + (uint32_t)((it - 1) % ANSTG) * ASTG_SZ;
            compute_Y(stg_prev, af_prev, accY, lane);
        }
#pragma unroll
        for (int a = 0; a < 4; a++)
#pragma unroll
            for (int bb2 = 0; bb2 < 4; bb2++) af_prev[a][bb2] = af_cur[a][bb2];

        // refill stage (it+2)%4 — overwrites stage it-2 (V consumed in iter it-1,
        // guaranteed done by this iteration's barrier)
        if (it + 2 < niter)
            load_kv_stage(sb + ASTG + (uint32_t)((it + 2) % ANSTG) * ASTG_SZ,
                          bh, (it + 2) * 64, tid);
    }
    // drain: final Y for tile niter-1 (its V stage untouched since load)
    compute_Y(sb + ASTG + (uint32_t)((niter - 1) % ANSTG) * ASTG_SZ,
              af_prev, accY, lane);

    // ---- write out[b, t, h*64 + d] ----
    const int q0 = qt * 128 + wm + (lane >> 2);
#pragma unroll
    for (int nt = 0; nt < 8; nt++) {
        int col = h * HS + nt * 8 + (lane & 3) * 2;
        *(float2*)(out + ((size_t)b * T_SEQ + q0) * C_DIM + col) =
            make_float2(accY[nt][0], accY[nt][1]);
        *(float2*)(out + ((size_t)b * T_SEQ + q0 + 8) * C_DIM + col) =
            make_float2(accY[nt][2], accY[nt][3]);
    }
}

// ---------------------------------------------------------------------------
extern "C" void kernel_launch(void* const* d_in, const int* in_sizes, int n_in,
                              void* d_out, int out_size)
{
    const float* x    = (const float*)d_in[0];
    const float* W    = (const float*)d_in[1];
    const float* bias = (const float*)d_in[2];
    float* out        = (float*)d_out;

    prep_x_kernel<<<(M_ROWS * C_DIM) / (256 * 8), 256>>>(x);
    prep_w_kernel<<<dim3(C3 / 32, C_DIM / 32), dim3(32, 8)>>>(W);

    cudaFuncSetAttribute(qkv_mma_kernel,
                         cudaFuncAttributeMaxDynamicSharedMemorySize, GEMM_SMEM);
    qkv_mma_kernel<<<dim3(C3 / 128, M_ROWS / 128), 256, GEMM_SMEM>>>(bias);

    cudaFuncSetAttribute(attn_mma_kernel,
                         cudaFuncAttributeMaxDynamicSharedMemorySize, ATTN_SMEM);
    attn_mma_kernel<<<dim3(8, NBH), 256, ATTN_SMEM>>>(out);
}

// round 17
// speedup vs baseline: 1.0368x; 1.0368x over previous
#include <cuda_runtime.h>
#include <cuda_fp16.h>
#include <cstdint>

#define B_SZ   8
#define T_SEQ  1024
#define C_DIM  768
#define C3     2304
#define NH     12
#define HS     64
#define SCALE_F 0.125f
#define M_ROWS (B_SZ * T_SEQ)       /* 8192 */
#define NBH    (B_SZ * NH)          /* 96 */

// fp16 operands: x [8192,768], W^T [2304,768] (K-contiguous)
__device__ __align__(16) __half g_xh[(size_t)M_ROWS * C_DIM];
__device__ __align__(16) __half g_wth[(size_t)C3 * C_DIM];
// head-separated QKV outputs, fp16: [bh, t, 64]. g_q is pre-scaled by 1/8.
#define QKV_ELEMS ((size_t)NBH * T_SEQ * HS)
__device__ __align__(16) __half g_q[QKV_ELEMS], g_k[QKV_ELEMS], g_v[QKV_ELEMS];

// ---------------------------------------------------------------------------
// helpers
// ---------------------------------------------------------------------------
__device__ __forceinline__ uint32_t smem_u32(const void* p) {
    uint32_t a;
    asm("{ .reg .u64 t; cvta.to.shared.u64 t, %1; cvt.u32.u64 %0, t; }"
        : "=r"(a) : "l"(p));
    return a;
}
#define SWZ128(off) ((off) ^ (((off) >> 3) & 0x70))

__device__ __forceinline__ void cp_async16(uint32_t saddr, const void* gaddr) {
    asm volatile("cp.async.cg.shared.global [%0], [%1], 16;"
                 :: "r"(saddr), "l"(gaddr) : "memory");
}
__device__ __forceinline__ void cp_commit() {
    asm volatile("cp.async.commit_group;" ::: "memory");
}
template <int N>
__device__ __forceinline__ void cp_wait() {
    asm volatile("cp.async.wait_group %0;" :: "n"(N) : "memory");
}
__device__ __forceinline__ void ldm_x4(uint32_t* r, uint32_t addr) {
    asm volatile("ldmatrix.sync.aligned.m8n8.x4.shared.b16 {%0,%1,%2,%3}, [%4];"
                 : "=r"(r[0]), "=r"(r[1]), "=r"(r[2]), "=r"(r[3]) : "r"(addr));
}
__device__ __forceinline__ void ldm_x4_t(uint32_t* r, uint32_t addr) {
    asm volatile("ldmatrix.sync.aligned.m8n8.x4.trans.shared.b16 {%0,%1,%2,%3}, [%4];"
                 : "=r"(r[0]), "=r"(r[1]), "=r"(r[2]), "=r"(r[3]) : "r"(addr));
}
__device__ __forceinline__ void mma_f16(float* c, const uint32_t* a,
                                        const uint32_t b0, const uint32_t b1) {
    asm volatile(
        "mma.sync.aligned.m16n8k16.row.col.f32.f16.f16.f32 "
        "{%0,%1,%2,%3}, {%4,%5,%6,%7}, {%8,%9}, {%0,%1,%2,%3};"
        : "+f"(c[0]), "+f"(c[1]), "+f"(c[2]), "+f"(c[3])
        : "r"(a[0]), "r"(a[1]), "r"(a[2]), "r"(a[3]), "r"(b0), "r"(b1));
}
__device__ __forceinline__ uint32_t pack_f16x2(float v0, float v1) {
    __half2 h = __floats2half2_rn(v0, v1);   // v0 -> low
    return *reinterpret_cast<uint32_t*>(&h);
}
// pack + relu in fp16x2 (identical numerics to cvt(max(v,0)))
__device__ __forceinline__ uint32_t pack_relu_f16x2(float v0, float v1) {
    __half2 h = __floats2half2_rn(v0, v1);
    h = __hmax2(h, __half2half2(__ushort_as_half(0)));
    return *reinterpret_cast<uint32_t*>(&h);
}

// ---------------------------------------------------------------------------
// Fused prep kernel: blocks [0, NXBLK) convert x (x8 vectorized);
// blocks [NXBLK, NXBLK+NWBLK) transpose+convert W. One wave, no serialization.
// ---------------------------------------------------------------------------
#define NXBLK ((M_ROWS * C_DIM) / (256 * 8))          /* 3072 */
#define NWB_X (C3 / 32)                               /* 72 */
#define NWB_Y (C_DIM / 32)                            /* 24 */
#define NWBLK (NWB_X * NWB_Y)                         /* 1728 */

__global__ __launch_bounds__(256) void prep_fused_kernel(
    const float* __restrict__ x, const float* __restrict__ W)
{
    __shared__ float t[32][33];
    const int tid = threadIdx.x;
    if (blockIdx.x < NXBLK) {
        // ---- x -> fp16, 8 elems/thread ----
        int i = (blockIdx.x * 256 + tid) * 8;
        float4 a = *(const float4*)(x + i);
        float4 b = *(const float4*)(x + i + 4);
        uint4 o;
        o.x = pack_f16x2(a.x, a.y);
        o.y = pack_f16x2(a.z, a.w);
        o.z = pack_f16x2(b.x, b.y);
        o.w = pack_f16x2(b.z, b.w);
        *(uint4*)(g_xh + i) = o;
    } else {
        // ---- W transpose + fp16 (exact R14 prep_w, flat-thread remap) ----
        int wb = blockIdx.x - NXBLK;
        int n0 = (wb % NWB_X) * 32, k0 = (wb / NWB_X) * 32;
        int tx = tid & 31, ty = tid >> 5;    // 32 x 8
#pragma unroll
        for (int j = 0; j < 4; j++)
            t[ty + 8 * j][tx] = W[(size_t)(k0 + ty + 8 * j) * C3 + n0 + tx];
        __syncthreads();
#pragma unroll
        for (int jj = 0; jj < 2; jj++) {
            int idx = jj * 256 + tid;        // 0..511
            int r   = idx >> 4;              // n-row 0..31
            int kp  = idx & 15;              // k-pair 0..15
            uint32_t v = pack_f16x2(t[2 * kp][r], t[2 * kp + 1][r]);
            *(uint32_t*)(g_wth + (size_t)(n0 + r) * C_DIM + k0 + 2 * kp) = v;
        }
    }
}

// ---------------------------------------------------------------------------
// Kernel 1: QKV projection, fp16 mma.sync (R14 exact, measured best).
// Block tile 128x128, K-chunk 64, 8 warps (warp 32x64), 2-stage, 2 CTA/SM.
// Epilogue: smem-staged, fully coalesced 128B-row stores.
// ---------------------------------------------------------------------------
#define BK       64
#define NCHUNK   (C_DIM / BK)          /* 12 */
#define TILE_B   (128 * 128)           /* 16 KB */
#define STAGE_B  (2 * TILE_B)          /* A + B = 32 KB */
#define GEMM_SMEM (2 * STAGE_B)        /* 64 KB */
#define EPI_STRIDE 72                  /* halves per staged row (pad: 64+8) */
#define EPI_WARP_B (32 * EPI_STRIDE * 2)   /* 4608 B per warp */

__device__ __forceinline__ void load_stage(uint32_t sbase, int bm, int bn,
                                           int k0, int tid)
{
#pragma unroll
    for (int i = 0; i < 8; i++) {
        int lin = i * 256 + tid;          // 0..2047
        int buf = lin >> 10;              // 0:A 1:B
        int idx = lin & 1023;
        int r   = idx >> 3;
        int cb  = (idx & 7) * 16;
        uint32_t sw = SWZ128((uint32_t)(r * 128 + cb));
        const char* src = buf
            ? (const char*)(g_wth + (size_t)(bn + r) * C_DIM + k0) + cb
            : (const char*)(g_xh  + (size_t)(bm + r) * C_DIM + k0) + cb;
        cp_async16(sbase + buf * TILE_B + sw, src);
    }
    cp_commit();
}

__global__ __launch_bounds__(256, 2) void qkv_mma_kernel(const float* __restrict__ bias)
{
    extern __shared__ char sm[];
    const uint32_t sbase = smem_u32(sm);

    const int tid  = threadIdx.x;
    const int wid  = tid >> 5;
    const int lane = tid & 31;
    const int bn   = blockIdx.x * 128;
    const int bm   = blockIdx.y * 128;
    const int warp_m = (wid & 3) * 32;
    const int warp_n = (wid >> 2) * 64;
    const int ldrow   = lane & 15;
    const int ldchunk = (lane >> 4) * 16;

    float acc[2][8][4];
#pragma unroll
    for (int mt = 0; mt < 2; mt++)
#pragma unroll
        for (int nt = 0; nt < 8; nt++)
#pragma unroll
            for (int q = 0; q < 4; q++) acc[mt][nt][q] = 0.f;

    load_stage(sbase, bm, bn, 0, tid);

    for (int ch = 0; ch < NCHUNK; ch++) {
        const uint32_t sstage = sbase + (uint32_t)(ch & 1) * STAGE_B;
        if (ch + 1 < NCHUNK) {
            load_stage(sbase + (uint32_t)((ch + 1) & 1) * STAGE_B,
                       bm, bn, (ch + 1) * BK, tid);
            cp_wait<1>();
        } else {
            cp_wait<0>();
        }
        __syncthreads();

#pragma unroll
        for (int ks = 0; ks < 4; ks++) {
            const int kb = ks * 32 + ldchunk;
            uint32_t a[2][4];
#pragma unroll
            for (int mt = 0; mt < 2; mt++) {
                uint32_t off = SWZ128((uint32_t)((warp_m + mt * 16 + ldrow) * 128 + kb));
                ldm_x4(a[mt], sstage + off);
            }
            uint32_t bv[8][2];
#pragma unroll
            for (int np = 0; np < 4; np++) {
                uint32_t off = SWZ128((uint32_t)((warp_n + np * 16 + ldrow) * 128 + kb));
                uint32_t r[4];
                ldm_x4(r, sstage + TILE_B + off);
                bv[2 * np][0] = r[0]; bv[2 * np][1] = r[2];
                bv[2 * np + 1][0] = r[1]; bv[2 * np + 1][1] = r[3];
            }
#pragma unroll
            for (int mt = 0; mt < 2; mt++)
#pragma unroll
                for (int nt = 0; nt < 8; nt++)
                    mma_f16(acc[mt][nt], a[mt], bv[nt][0], bv[nt][1]);
        }
        __syncthreads();
    }

    // ---- Epilogue: bias + stage to smem, then coalesced 128B-row stores ----
    const int col0  = bn + warp_n;            // 64-aligned
    const int which = col0 / C_DIM;
    const int hh    = (col0 % C_DIM) / HS;
    __half* dst = (which == 0) ? g_q : (which == 1) ? g_k : g_v;
    const float scl = (which == 0) ? SCALE_F : 1.f;

    char* wst = sm + wid * EPI_WARP_B;
    const int crow = lane >> 2;
    const int ccol = (lane & 3) * 2;
#pragma unroll
    for (int mt = 0; mt < 2; mt++) {
#pragma unroll
        for (int nt = 0; nt < 8; nt++) {
            int ncol = nt * 8 + ccol;
            float2 bb = *(const float2*)(bias + col0 + ncol);
#pragma unroll
            for (int p = 0; p < 2; p++) {
                int lrow = mt * 16 + p * 8 + crow;
                uint32_t hv = pack_f16x2((acc[mt][nt][2 * p + 0] + bb.x) * scl,
                                         (acc[mt][nt][2 * p + 1] + bb.y) * scl);
                *(uint32_t*)(wst + (lrow * EPI_STRIDE + ncol) * 2) = hv;
            }
        }
    }
    __syncwarp();

    const int rbase = bm + warp_m;
#pragma unroll
    for (int it = 0; it < 8; it++) {
        int idx = it * 32 + lane;
        int lrow = idx >> 3;
        int chk  = idx & 7;
        int r = rbase + lrow;
        int bidx = r >> 10, t = r & 1023;
        size_t off = (((size_t)(bidx * NH + hh)) * T_SEQ + t) * HS + chk * 8;
        uint4 v = *(uint4*)(wst + (lrow * EPI_STRIDE + chk * 8) * 2);
        *(uint4*)(dst + off) = v;
    }
}

// ---------------------------------------------------------------------------
// Kernel 2: causal relu-attention, fp16 mma.sync (R14 exact, measured best).
// Block = (bh, 128 q-rows); 8 warps x 16 q-rows; kv-tile 64, double-buffered.
// Q fragments resident in registers. 2 CTAs/SM.
// ---------------------------------------------------------------------------
#define AQ      0
#define ASTG    16384
#define ASTG_SZ 16384                  /* K 8KB + V 8KB */
#define AK      0
#define AV      8192
#define ATTN_SMEM (ASTG + 2 * ASTG_SZ) /* 48 KB */

__device__ __forceinline__ void load_kv_stage(uint32_t dst, int bh, int kv0, int tid) {
#pragma unroll
    for (int i = 0; i < 4; i++) {
        int lin = i * 256 + tid;          // 0..1023
        int buf = lin >> 9;               // 0:K 1:V
        int idx = lin & 511;
        int r = idx >> 3, cb = (idx & 7) * 16;
        uint32_t sw = SWZ128((uint32_t)(r * 128 + cb));
        const __half* src = buf ? g_v : g_k;
        cp_async16(dst + buf * 8192 + sw,
                   (const char*)(src + ((size_t)bh * T_SEQ + kv0 + r) * HS) + cb);
    }
    cp_commit();
}

__global__ __launch_bounds__(256, 2) void attn_mma_kernel(float* __restrict__ out)
{
    extern __shared__ char sm[];
    const uint32_t sb = smem_u32(sm);
    const int tid = threadIdx.x, wid = tid >> 5, lane = tid & 31;
    const int qt = gridDim.x - 1 - blockIdx.x;   // heavy blocks first
    const int bh = blockIdx.y;
    const int b = bh / NH, h = bh % NH;
    const int wm = wid * 16;                     // warp owns 16 q-rows

    // Q tile load (128 rows x 64 fp16) — group 1
#pragma unroll
    for (int i = 0; i < 4; i++) {
        int idx = i * 256 + tid;
        int r = idx >> 3, cb = (idx & 7) * 16;
        uint32_t sw = SWZ128((uint32_t)(r * 128 + cb));
        cp_async16(sb + AQ + sw,
                   (const char*)(g_q + ((size_t)bh * T_SEQ + qt * 128 + r) * HS) + cb);
    }
    cp_commit();
    load_kv_stage(sb + ASTG, bh, 0, tid);   // group 2

    // Wait for Q only (leave kv0 pending), publish, lift Q frags to registers.
    cp_wait<1>();
    __syncthreads();
    uint32_t qf[4][4];
#pragma unroll
    for (int ks = 0; ks < 4; ks++) {
        uint32_t qoff = SWZ128((uint32_t)((wm + (lane & 15)) * 128
                                          + ks * 32 + (lane >> 4) * 16));
        ldm_x4(qf[ks], sb + AQ + qoff);
    }

    float accY[8][4];
#pragma unroll
    for (int nt = 0; nt < 8; nt++)
#pragma unroll
        for (int q = 0; q < 4; q++) accY[nt][q] = 0.f;

    const int niter = 2 * qt + 2;
    for (int it = 0; it < niter; it++) {
        __syncthreads();
        if (it + 1 < niter) {
            load_kv_stage(sb + ASTG + (uint32_t)((it + 1) & 1) * ASTG_SZ,
                          bh, (it + 1) * 64, tid);
            cp_wait<1>();
        } else {
            cp_wait<0>();
        }
        __syncthreads();

        const uint32_t stg = sb + ASTG + (uint32_t)(it & 1) * ASTG_SZ;
        const bool nomask = (it < 2 * qt);

        uint32_t af[4][4];

#pragma unroll
        for (int hf = 0; hf < 2; hf++) {
            float s[4][4];
#pragma unroll
            for (int j = 0; j < 4; j++)
#pragma unroll
                for (int q = 0; q < 4; q++) s[j][q] = 0.f;

#pragma unroll
            for (int ks = 0; ks < 4; ks++) {
                const int kb = ks * 32 + (lane >> 4) * 16;
                uint32_t kf[4][2];
#pragma unroll
                for (int npl = 0; npl < 2; npl++) {
                    int np = 2 * hf + npl;
                    uint32_t koff = SWZ128((uint32_t)(
                        (np * 16 + (lane & 15)) * 128 + kb));
                    uint32_t r[4];
                    ldm_x4(r, stg + AK + koff);
                    kf[2 * npl][0] = r[0]; kf[2 * npl][1] = r[2];
                    kf[2 * npl + 1][0] = r[1]; kf[2 * npl + 1][1] = r[3];
                }
#pragma unroll
                for (int j = 0; j < 4; j++)
                    mma_f16(s[j], qf[ks], kf[j][0], kf[j][1]);
            }

            if (nomask) {
#pragma unroll
                for (int j = 0; j < 4; j++) {
                    int nt = 4 * hf + j;
#pragma unroll
                    for (int p = 0; p < 2; p++)
                        af[nt >> 1][(nt & 1) * 2 + p] =
                            pack_relu_f16x2(s[j][2 * p + 0], s[j][2 * p + 1]);
                }
            } else {
                int q0 = qt * 128 + wm + (lane >> 2);
#pragma unroll
                for (int j = 0; j < 4; j++) {
                    int nt  = 4 * hf + j;
                    int kv0 = it * 64 + nt * 8 + (lane & 3) * 2;
#pragma unroll
                    for (int p = 0; p < 2; p++) {
                        int qq = q0 + p * 8;
                        float v0 = (kv0     <= qq) ? fmaxf(s[j][2 * p + 0], 0.f) : 0.f;
                        float v1 = (kv0 + 1 <= qq) ? fmaxf(s[j][2 * p + 1], 0.f) : 0.f;
                        af[nt >> 1][(nt & 1) * 2 + p] = pack_f16x2(v0, v1);
                    }
                }
            }
        }

#pragma unroll
        for (int ks = 0; ks < 4; ks++) {
#pragma unroll
            for (int np = 0; np < 4; np++) {
                uint32_t voff = SWZ128((uint32_t)(
                    (ks * 16 + (lane & 7) + ((lane >> 4) & 1) * 8) * 128
                    + np * 32 + ((lane >> 3) & 1) * 16));
                uint32_t vf[4];
                ldm_x4_t(vf, stg + AV + voff);
                mma_f16(accY[2 * np],     af[ks], vf[0], vf[2]);
                mma_f16(accY[2 * np + 1], af[ks], vf[1], vf[3]);
            }
        }
    }

    const int q0 = qt * 128 + wm + (lane >> 2);
#pragma unroll
    for (int nt = 0; nt < 8; nt++) {
        int col = h * HS + nt * 8 + (lane & 3) * 2;
        *(float2*)(out + ((size_t)b * T_SEQ + q0) * C_DIM + col) =
            make_float2(accY[nt][0], accY[nt][1]);
        *(float2*)(out + ((size_t)b * T_SEQ + q0 + 8) * C_DIM + col) =
            make_float2(accY[nt][2], accY[nt][3]);
    }
}

// ---------------------------------------------------------------------------
extern "C" void kernel_launch(void* const* d_in, const int* in_sizes, int n_in,
                              void* d_out, int out_size)
{
    const float* x    = (const float*)d_in[0];
    const float* W    = (const float*)d_in[1];
    const float* bias = (const float*)d_in[2];
    float* out        = (float*)d_out;

    prep_fused_kernel<<<NXBLK + NWBLK, 256>>>(x, W);

    cudaFuncSetAttribute(qkv_mma_kernel,
                         cudaFuncAttributeMaxDynamicSharedMemorySize, GEMM_SMEM);
    qkv_mma_kernel<<<dim3(C3 / 128, M_ROWS / 128), 256, GEMM_SMEM>>>(bias);

    cudaFuncSetAttribute(attn_mma_kernel,
                         cudaFuncAttributeMaxDynamicSharedMemorySize, ATTN_SMEM);
    attn_mma_kernel<<<dim3(8, NBH), 256, ATTN_SMEM>>>(out);
}